// round 4
// baseline (speedup 1.0000x reference)
#include <cuda_runtime.h>

// Problem constants (fixed by setup_inputs)
#define H   80
#define B   4096
#define T   512
#define RPB 32              // rows (batch) per CTA
#define NCTA (B / RPB)      // 128
#define NTHR 320            // two independent 160-thread groups of (j, rblk)
#define GSZ  160            // threads per group (5 warps)

// Packed weight layout (floats):
//   layer 1: k in [0,81)  : Wp[(k*80+j)*4 + g], k=0 -> x weight, k>=1 -> h1 weight (col k-1)
//   layer l>=2: k in [0,160): k<80 -> w_ih col k (input h_{l-1}), k>=80 -> w_hh col k-80 (own h)
#define OFF1 0
#define OFF2 25920          // 81*320
#define OFF3 77120          // OFF2 + 160*320
#define OFF4 128320
#define WTOT 179520
#define BTOT 1280           // 4 layers * 320 (bias, gate-interleaved [l][j][g])

__device__ float g_Wp[WTOT];
__device__ float g_Bp[BTOT];

typedef unsigned long long u64;

__device__ __forceinline__ u64 dup2(float w) {
    u64 r; unsigned u = __float_as_uint(w);
    asm("mov.b64 %0, {%1, %1};" : "=l"(r) : "r"(u));
    return r;
}
__device__ __forceinline__ void fma2(u64 &d, u64 a, u64 b) {
    asm("fma.rn.f32x2 %0, %1, %2, %0;" : "+l"(d) : "l"(a), "l"(b));
}
__device__ __forceinline__ float lo32(u64 v) { return __uint_as_float((unsigned)v); }
__device__ __forceinline__ float hi32(u64 v) { return __uint_as_float((unsigned)(v >> 32)); }

__device__ __forceinline__ float tanhap(float x) {
    float y; asm("tanh.approx.f32 %0, %1;" : "=f"(y) : "f"(x)); return y;
}
__device__ __forceinline__ float sigf(float x) {
    return fmaf(0.5f, tanhap(0.5f * x), 0.5f);   // sigmoid via 1 MUFU
}

// One k-slice for 8 rows: 4 gate weights x 8 h values -> 16 FFMA2
// acc layout: acc[4g + p] = gate g, row pair p (rows 2p, 2p+1)
__device__ __forceinline__ void fmak8(u64 *acc, float4 w, ulonglong2 ha, ulonglong2 hb) {
    u64 w0 = dup2(w.x), w1 = dup2(w.y), w2 = dup2(w.z), w3 = dup2(w.w);
    fma2(acc[0],  w0, ha.x); fma2(acc[1],  w0, ha.y); fma2(acc[2],  w0, hb.x); fma2(acc[3],  w0, hb.y);
    fma2(acc[4],  w1, ha.x); fma2(acc[5],  w1, ha.y); fma2(acc[6],  w1, hb.x); fma2(acc[7],  w1, hb.y);
    fma2(acc[8],  w2, ha.x); fma2(acc[9],  w2, ha.y); fma2(acc[10], w2, hb.x); fma2(acc[11], w2, hb.y);
    fma2(acc[12], w3, ha.x); fma2(acc[13], w3, ha.y); fma2(acc[14], w3, hb.x); fma2(acc[15], w3, hb.y);
}

// Pipelined NK-wide gemm with one-chunk-ahead prefetch of weights (LDG) and h (LDS).
// k < 80 reads hA, k >= 80 reads hB. W is float4[k][80], k in [0, NK).
// roff selects the thread's 8 rows within the 32-row CTA tile.
template<int NK>
__device__ __forceinline__ void gemmN(u64 *acc, const float4 *__restrict__ W,
                                      const float *__restrict__ hA,
                                      const float *__restrict__ hB, int j, int roff) {
    float4     wb[2][4];
    ulonglong2 hb[2][4][2];
#pragma unroll
    for (int q = 0; q < 4; q++) {
        wb[0][q] = W[q * 80 + j];
        const ulonglong2 *hv = (const ulonglong2 *)(hA + q * RPB + roff);
        hb[0][q][0] = hv[0]; hb[0][q][1] = hv[1];
    }
#pragma unroll 4
    for (int kk = 0; kk < NK; kk += 4) {
        const int cur = (kk >> 2) & 1;
        const int nxt = cur ^ 1;
        const int kn  = kk + 4;
        if (kn < NK) {
            const float *hp = (kn < 80) ? hA : hB;
            const int    ho = (kn < 80) ? kn : (kn - 80);
#pragma unroll
            for (int q = 0; q < 4; q++) {
                wb[nxt][q] = W[(kn + q) * 80 + j];
                const ulonglong2 *hv = (const ulonglong2 *)(hp + (ho + q) * RPB + roff);
                hb[nxt][q][0] = hv[0]; hb[nxt][q][1] = hv[1];
            }
        }
#pragma unroll
        for (int q = 0; q < 4; q++)
            fmak8(acc, wb[cur][q], hb[cur][q][0], hb[cur][q][1]);
    }
}

// LSTM elementwise for 8 rows; c is 8-row cell state in registers
__device__ __forceinline__ void cell(const u64 *acc, float *c, float *hdst, int j, int roff) {
    float hv[8];
#pragma unroll
    for (int qq = 0; qq < 8; qq++) {
        int pp = qq >> 1;
        float iv, fv, gv, ov;
        if (qq & 1) {
            iv = hi32(acc[0 + pp]); fv = hi32(acc[4 + pp]);
            gv = hi32(acc[8 + pp]); ov = hi32(acc[12 + pp]);
        } else {
            iv = lo32(acc[0 + pp]); fv = lo32(acc[4 + pp]);
            gv = lo32(acc[8 + pp]); ov = lo32(acc[12 + pp]);
        }
        float cc = sigf(fv) * c[qq] + sigf(iv) * tanhap(gv);
        c[qq] = cc;
        hv[qq] = sigf(ov) * tanhap(cc);
    }
    float4 *d = (float4 *)(hdst + j * RPB + roff);
    d[0] = make_float4(hv[0], hv[1], hv[2], hv[3]);
    d[1] = make_float4(hv[4], hv[5], hv[6], hv[7]);
}

__device__ __forceinline__ void acc_init(u64 *acc, float4 b) {
    u64 b0 = dup2(b.x), b1 = dup2(b.y), b2 = dup2(b.z), b3 = dup2(b.w);
#pragma unroll
    for (int p = 0; p < 4; p++) { acc[0 + p] = b0; acc[4 + p] = b1; acc[8 + p] = b2; acc[12 + p] = b3; }
}

// ---------------------------------------------------------------------------
// Weight/bias repack kernel: transpose + gate-interleave into g_Wp / g_Bp
// ---------------------------------------------------------------------------
__global__ void pack_kernel(
    const float *wih1, const float *whh1, const float *bih1, const float *bhh1,
    const float *wih2, const float *whh2, const float *bih2, const float *bhh2,
    const float *wih3, const float *whh3, const float *bih3, const float *bhh3,
    const float *wih4, const float *whh4, const float *bih4, const float *bhh4) {
    int idx = blockIdx.x * blockDim.x + threadIdx.x;
    const float *wih[4] = {wih1, wih2, wih3, wih4};
    const float *whh[4] = {whh1, whh2, whh3, whh4};
    const float *bih[4] = {bih1, bih2, bih3, bih4};
    const float *bhh[4] = {bhh1, bhh2, bhh3, bhh4};
    if (idx < WTOT) {
        int l, off;
        if (idx < OFF2)      { l = 0; off = OFF1; }
        else if (idx < OFF3) { l = 1; off = OFF2; }
        else if (idx < OFF4) { l = 2; off = OFF3; }
        else                 { l = 3; off = OFF4; }
        int e = idx - off;
        int g = e & 3;
        int j = (e >> 2) % 80;
        int k = e / 320;
        int row = g * 80 + j;
        float v;
        if (l == 0) v = (k == 0) ? wih[0][row] : whh[0][row * 80 + (k - 1)];
        else        v = (k < 80) ? wih[l][row * 80 + k] : whh[l][row * 80 + (k - 80)];
        g_Wp[idx] = v;
    } else if (idx < WTOT + BTOT) {
        int e = idx - WTOT;
        int g = e & 3;
        int j = (e >> 2) % 80;
        int l = e / 320;
        int row = g * 80 + j;
        g_Bp[e] = bih[l][row] + bhh[l][row];
    }
}

// ---------------------------------------------------------------------------
// Main persistent LSTM kernel: each CTA owns 32 rows, split into TWO fully
// independent 160-thread streams (rows 0-15 / 16-31) using named barriers so
// one stream's FMA work fills the other's MUFU / barrier / latency gaps.
// ---------------------------------------------------------------------------
#define SMEM_FLOATS (4 * 2 * H * RPB + RPB + H + BTOT)
#define SMEM_BYTES  (SMEM_FLOATS * 4)

__global__ void __launch_bounds__(NTHR, 1) lstm4_kernel(
    const float *__restrict__ input,  // (B, T)
    const float *__restrict__ wlin,   // (80)
    const float *__restrict__ blin,   // (1)
    float *__restrict__ out) {        // (B, T)
    extern __shared__ float sm[];
    float *hs_base = sm;                          // [4][2][80][32]
    float *x_s     = sm + 4 * 2 * H * RPB;        // [32]
    float *wlin_s  = x_s + RPB;                   // [80]
    float *bias_s  = wlin_s + H;                  // [4][80][4] gate-interleaved

    const int tid  = threadIdx.x;
    const int grp  = tid / GSZ;                   // 0 or 1 (warps 0-4 / 5-9)
    const int gt   = tid % GSZ;
    const int j    = gt % 80;
    const int rblk = gt / 80;                     // 0..1
    const int roff = grp * 16 + rblk * 8;         // this thread's 8 rows
    const int b0   = blockIdx.x * RPB;
    const int bar_id = grp + 1;                   // named barrier 1 or 2

    for (int i = tid; i < 4 * 2 * H * RPB; i += NTHR) hs_base[i] = 0.0f;
    if (tid < H) wlin_s[tid] = wlin[tid];
    for (int i = tid; i < BTOT; i += NTHR) bias_s[i] = g_Bp[i];
    const float blin_v = blin[0];

    float c[4][8];
#pragma unroll
    for (int l = 0; l < 4; l++)
#pragma unroll
        for (int qq = 0; qq < 8; qq++) c[l][qq] = 0.0f;

    const float4 *W1 = (const float4 *)(g_Wp + OFF1);
    const float4 *W2 = (const float4 *)(g_Wp + OFF2);
    const float4 *W3 = (const float4 *)(g_Wp + OFF3);
    const float4 *W4 = (const float4 *)(g_Wp + OFF4);
    const float4 *bias4 = (const float4 *)bias_s;

    __syncthreads();   // smem init visible to both groups

#define GBAR() asm volatile("bar.sync %0, %1;" :: "r"(bar_id), "n"(GSZ) : "memory")

    for (int t = 0; t < T; t++) {
        const int p = t & 1;       // write buffer this step
        const int q = p ^ 1;       // own-h read buffer (previous step)
        float *h1n = hs_base + (0 * 2 + p) * H * RPB;
        const float *h1o = hs_base + (0 * 2 + q) * H * RPB;
        float *h2n = hs_base + (1 * 2 + p) * H * RPB;
        const float *h2o = hs_base + (1 * 2 + q) * H * RPB;
        float *h3n = hs_base + (2 * 2 + p) * H * RPB;
        const float *h3o = hs_base + (2 * 2 + q) * H * RPB;
        float *h4n = hs_base + (3 * 2 + p) * H * RPB;
        const float *h4o = hs_base + (3 * 2 + q) * H * RPB;

        // group loads its own 16 input scalars
        if (gt < 16) {
            int r = grp * 16 + gt;
            x_s[r] = input[(b0 + r) * T + t];
        }
        GBAR();

        u64 acc[16];

        // ----- layer 1 (input: scalar x, own h1) -----
        acc_init(acc, bias4[0 * 80 + j]);
        {
            const ulonglong2 *xv = (const ulonglong2 *)(x_s + roff);
            fmak8(acc, W1[j], xv[0], xv[1]);   // k = 0: x weight
        }
        gemmN<80>(acc, W1 + 80, h1o, h1o, j, roff);   // k = 1..80: recurrent
        cell(acc, c[0], h1n, j, roff);
        GBAR();

        // ----- layer 2 (fused 160-wide gemm: input h1n, own h2o) -----
        acc_init(acc, bias4[1 * 80 + j]);
        gemmN<160>(acc, W2, h1n, h2o, j, roff);
        cell(acc, c[1], h2n, j, roff);
        GBAR();

        // output head: out[b, t] = w_lin . h2_new[b] + b_lin (16 threads/group)
        if (gt < 16) {
            int r = grp * 16 + gt;
            float s = blin_v;
#pragma unroll 8
            for (int jj = 0; jj < H; jj++) s = fmaf(wlin_s[jj], h2n[jj * RPB + r], s);
            out[(b0 + r) * T + t] = s;
        }

        // ----- layer 3 -----
        acc_init(acc, bias4[2 * 80 + j]);
        gemmN<160>(acc, W3, h2n, h3o, j, roff);
        cell(acc, c[2], h3n, j, roff);
        GBAR();

        // ----- layer 4 -----
        acc_init(acc, bias4[3 * 80 + j]);
        gemmN<160>(acc, W4, h3n, h4o, j, roff);
        cell(acc, c[3], h4n, j, roff);
        // no trailing barrier: next step's GBAR after x_s write orders h4n
    }
#undef GBAR
}

extern "C" void kernel_launch(void *const *d_in, const int *in_sizes, int n_in,
                              void *d_out, int out_size) {
    const float *input = (const float *)d_in[0];
    const float *wlin  = (const float *)d_in[17];
    const float *blin  = (const float *)d_in[18];

    pack_kernel<<<(WTOT + BTOT + 255) / 256, 256>>>(
        (const float *)d_in[1],  (const float *)d_in[2],  (const float *)d_in[3],  (const float *)d_in[4],
        (const float *)d_in[5],  (const float *)d_in[6],  (const float *)d_in[7],  (const float *)d_in[8],
        (const float *)d_in[9],  (const float *)d_in[10], (const float *)d_in[11], (const float *)d_in[12],
        (const float *)d_in[13], (const float *)d_in[14], (const float *)d_in[15], (const float *)d_in[16]);

    cudaFuncSetAttribute(lstm4_kernel, cudaFuncAttributeMaxDynamicSharedMemorySize, SMEM_BYTES);
    lstm4_kernel<<<NCTA, NTHR, SMEM_BYTES>>>(input, wlin, blin, (float *)d_out);
}

// round 5
// speedup vs baseline: 1.0387x; 1.0387x over previous
#include <cuda_runtime.h>

// Problem constants (fixed by setup_inputs)
#define H   80
#define B   4096
#define T   512
#define RPB 32              // rows (batch) per CTA
#define NCTA (B / RPB)      // 128
#define NTHR 320            // thread = (j in [0,80), rblk in [0,4)), 8 rows each

// Packed weight layout (floats):
//   layer 1: k in [0,81)  : Wp[(k*80+j)*4 + g], k=0 -> x weight, k>=1 -> h1 weight (col k-1)
//   layer l>=2: k in [0,160): k<80 -> w_ih col k (input h_{l-1}), k>=80 -> w_hh col k-80 (own h)
#define OFF1 0
#define OFF2 25920          // 81*320
#define OFF3 77120          // OFF2 + 160*320
#define OFF4 128320
#define WTOT 179520
#define BTOT 1280           // 4 layers * 320 (bias, gate-interleaved [l][j][g])

__device__ float g_Wp[WTOT];
__device__ float g_Bp[BTOT];

typedef unsigned long long u64;

__device__ __forceinline__ u64 dup2(float w) {
    u64 r; unsigned u = __float_as_uint(w);
    asm("mov.b64 %0, {%1, %1};" : "=l"(r) : "r"(u));
    return r;
}
__device__ __forceinline__ void fma2(u64 &d, u64 a, u64 b) {
    asm("fma.rn.f32x2 %0, %1, %2, %0;" : "+l"(d) : "l"(a), "l"(b));
}
__device__ __forceinline__ float lo32(u64 v) { return __uint_as_float((unsigned)v); }
__device__ __forceinline__ float hi32(u64 v) { return __uint_as_float((unsigned)(v >> 32)); }

__device__ __forceinline__ float tanhap(float x) {
    float y; asm("tanh.approx.f32 %0, %1;" : "=f"(y) : "f"(x)); return y;
}
__device__ __forceinline__ float sigf(float x) {
    return fmaf(0.5f, tanhap(0.5f * x), 0.5f);   // sigmoid via 1 MUFU
}

// One k-slice for 8 rows: 4 gate weights x 8 h values -> 16 FFMA2
// acc layout: acc[4g + p] = gate g, row pair p (rows 2p, 2p+1)
__device__ __forceinline__ void fmak8(u64 *acc, float4 w, ulonglong2 ha, ulonglong2 hb) {
    u64 w0 = dup2(w.x), w1 = dup2(w.y), w2 = dup2(w.z), w3 = dup2(w.w);
    fma2(acc[0],  w0, ha.x); fma2(acc[1],  w0, ha.y); fma2(acc[2],  w0, hb.x); fma2(acc[3],  w0, hb.y);
    fma2(acc[4],  w1, ha.x); fma2(acc[5],  w1, ha.y); fma2(acc[6],  w1, hb.x); fma2(acc[7],  w1, hb.y);
    fma2(acc[8],  w2, ha.x); fma2(acc[9],  w2, ha.y); fma2(acc[10], w2, hb.x); fma2(acc[11], w2, hb.y);
    fma2(acc[12], w3, ha.x); fma2(acc[13], w3, ha.y); fma2(acc[14], w3, hb.x); fma2(acc[15], w3, hb.y);
}

// Load one 4-k weight chunk (4 float4) for unit j
__device__ __forceinline__ void ldw4(float4 (&wt)[4], const float4 *__restrict__ W, int k0, int j) {
#pragma unroll
    for (int q = 0; q < 4; q++) wt[q] = W[(k0 + q) * 80 + j];
}

// 80-wide gemm half with distance-2 weight prefetch (4 rotating chunk slots)
// and 1-k-ahead h prefetch. Caller must have preloaded wb[0] (k 0..3) and
// wb[1] (k 4..7) BEFORE calling (ideally before the preceding cell/barrier).
__device__ __forceinline__ void gemm80p(u64 *acc, const float4 *__restrict__ W,
                                        float4 (&wb)[4][4],
                                        const float *__restrict__ hsrc, int j, int roff) {
    ulonglong2 hc0, hc1;
    { const ulonglong2 *p = (const ulonglong2 *)(hsrc + roff); hc0 = p[0]; hc1 = p[1]; }
#pragma unroll 1
    for (int c4 = 0; c4 < 16; c4 += 4) {
#pragma unroll
        for (int u = 0; u < 4; u++) {
            const int c = c4 + u;                       // chunk index, c&3 == u
            ldw4(wb[(u + 2) & 3], W, (c + 2) * 4, j);   // prefetch chunk c+2
#pragma unroll
            for (int kq = 0; kq < 4; kq++) {
                const int k = c * 4 + kq;
                const ulonglong2 *p = (const ulonglong2 *)(hsrc + (k + 1) * RPB + roff);
                ulonglong2 hn0 = p[0], hn1 = p[1];      // prefetch h(k+1), k+1 <= 64
                fmak8(acc, wb[u][kq], hc0, hc1);
                hc0 = hn0; hc1 = hn1;
            }
        }
    }
    // epilogue: chunks 16..19 (weight prefetch only for 18,19; h stops at k=79)
#pragma unroll
    for (int u = 0; u < 4; u++) {
        const int c = 16 + u;
        if (u < 2) ldw4(wb[(u + 2) & 3], W, (c + 2) * 4, j);
#pragma unroll
        for (int kq = 0; kq < 4; kq++) {
            const int k = c * 4 + kq;
            ulonglong2 hn0 = hc0, hn1 = hc1;
            if (k < 79) {
                const ulonglong2 *p = (const ulonglong2 *)(hsrc + (k + 1) * RPB + roff);
                hn0 = p[0]; hn1 = p[1];
            }
            fmak8(acc, wb[u][kq], hc0, hc1);
            hc0 = hn0; hc1 = hn1;
        }
    }
}

// LSTM elementwise for 8 rows; c is 8-row cell state in registers
__device__ __forceinline__ void cell(const u64 *acc, float *c, float *hdst, int j, int roff) {
    float hv[8];
#pragma unroll
    for (int qq = 0; qq < 8; qq++) {
        int pp = qq >> 1;
        float iv, fv, gv, ov;
        if (qq & 1) {
            iv = hi32(acc[0 + pp]); fv = hi32(acc[4 + pp]);
            gv = hi32(acc[8 + pp]); ov = hi32(acc[12 + pp]);
        } else {
            iv = lo32(acc[0 + pp]); fv = lo32(acc[4 + pp]);
            gv = lo32(acc[8 + pp]); ov = lo32(acc[12 + pp]);
        }
        float cc = sigf(fv) * c[qq] + sigf(iv) * tanhap(gv);
        c[qq] = cc;
        hv[qq] = sigf(ov) * tanhap(cc);
    }
    float4 *d = (float4 *)(hdst + j * RPB + roff);
    d[0] = make_float4(hv[0], hv[1], hv[2], hv[3]);
    d[1] = make_float4(hv[4], hv[5], hv[6], hv[7]);
}

__device__ __forceinline__ void acc_init(u64 *acc, float4 b) {
    u64 b0 = dup2(b.x), b1 = dup2(b.y), b2 = dup2(b.z), b3 = dup2(b.w);
#pragma unroll
    for (int p = 0; p < 4; p++) { acc[0 + p] = b0; acc[4 + p] = b1; acc[8 + p] = b2; acc[12 + p] = b3; }
}

// ---------------------------------------------------------------------------
// Weight/bias repack kernel: transpose + gate-interleave into g_Wp / g_Bp
// ---------------------------------------------------------------------------
__global__ void pack_kernel(
    const float *wih1, const float *whh1, const float *bih1, const float *bhh1,
    const float *wih2, const float *whh2, const float *bih2, const float *bhh2,
    const float *wih3, const float *whh3, const float *bih3, const float *bhh3,
    const float *wih4, const float *whh4, const float *bih4, const float *bhh4) {
    int idx = blockIdx.x * blockDim.x + threadIdx.x;
    const float *wih[4] = {wih1, wih2, wih3, wih4};
    const float *whh[4] = {whh1, whh2, whh3, whh4};
    const float *bih[4] = {bih1, bih2, bih3, bih4};
    const float *bhh[4] = {bhh1, bhh2, bhh3, bhh4};
    if (idx < WTOT) {
        int l, off;
        if (idx < OFF2)      { l = 0; off = OFF1; }
        else if (idx < OFF3) { l = 1; off = OFF2; }
        else if (idx < OFF4) { l = 2; off = OFF3; }
        else                 { l = 3; off = OFF4; }
        int e = idx - off;
        int g = e & 3;
        int j = (e >> 2) % 80;
        int k = e / 320;
        int row = g * 80 + j;
        float v;
        if (l == 0) v = (k == 0) ? wih[0][row] : whh[0][row * 80 + (k - 1)];
        else        v = (k < 80) ? wih[l][row * 80 + k] : whh[l][row * 80 + (k - 80)];
        g_Wp[idx] = v;
    } else if (idx < WTOT + BTOT) {
        int e = idx - WTOT;
        int g = e & 3;
        int j = (e >> 2) % 80;
        int l = e / 320;
        int row = g * 80 + j;
        g_Bp[e] = bih[l][row] + bhh[l][row];
    }
}

// ---------------------------------------------------------------------------
// Main persistent LSTM kernel. Per step, per layer: own-h half gemm FIRST
// (no dependency on previous layer), then barrier, then input-half gemm,
// then cell. Next gemm's first 2 weight chunks prefetched before each
// cell/barrier so gemm entry never stalls on L2.
// ---------------------------------------------------------------------------
#define SMEM_FLOATS (4 * 2 * H * RPB + RPB + H + BTOT)
#define SMEM_BYTES  (SMEM_FLOATS * 4)

__global__ void __launch_bounds__(NTHR, 1) lstm4_kernel(
    const float *__restrict__ input,  // (B, T)
    const float *__restrict__ wlin,   // (80)
    const float *__restrict__ blin,   // (1)
    float *__restrict__ out) {        // (B, T)
    extern __shared__ float sm[];
    float *hs_base = sm;                          // [4][2][80][32]
    float *x_s     = sm + 4 * 2 * H * RPB;        // [32]
    float *wlin_s  = x_s + RPB;                   // [80]
    float *bias_s  = wlin_s + H;                  // [4][80][4] gate-interleaved

    const int tid  = threadIdx.x;
    const int j    = tid % 80;
    const int rblk = tid / 80;                    // 0..3
    const int roff = rblk * 8;
    const int b0   = blockIdx.x * RPB;

    for (int i = tid; i < 4 * 2 * H * RPB; i += NTHR) hs_base[i] = 0.0f;
    if (tid < H) wlin_s[tid] = wlin[tid];
    for (int i = tid; i < BTOT; i += NTHR) bias_s[i] = g_Bp[i];
    const float blin_v = blin[0];

    float c[4][8];
#pragma unroll
    for (int l = 0; l < 4; l++)
#pragma unroll
        for (int qq = 0; qq < 8; qq++) c[l][qq] = 0.0f;

    // weight block pointers (float4[k][80], gate-interleaved)
    const float4 *W1x   = (const float4 *)(g_Wp + OFF1);           // k=0 (x slice)
    const float4 *W1own = W1x + 80;                                 // 80 k
    const float4 *W2in  = (const float4 *)(g_Wp + OFF2);            // 80 k
    const float4 *W2own = W2in + 80 * 80;
    const float4 *W3in  = (const float4 *)(g_Wp + OFF3);
    const float4 *W3own = W3in + 80 * 80;
    const float4 *W4in  = (const float4 *)(g_Wp + OFF4);
    const float4 *W4own = W4in + 80 * 80;
    const float4 *bias4 = (const float4 *)bias_s;

    float4 wb[4][4];                 // rotating weight chunk slots
    float4 w1x = W1x[j];             // x-slice weight, loop-invariant

    __syncthreads();

    // prologue prefetch for first gemm (L1 own)
    ldw4(wb[0], W1own, 0, j);
    ldw4(wb[1], W1own, 4, j);

    for (int t = 0; t < T; t++) {
        const int p = t & 1;       // write buffer this step
        const int q = p ^ 1;       // read buffer (previous step)
        float *h1n = hs_base + (0 * 2 + p) * H * RPB;
        const float *h1o = hs_base + (0 * 2 + q) * H * RPB;
        float *h2n = hs_base + (1 * 2 + p) * H * RPB;
        const float *h2o = hs_base + (1 * 2 + q) * H * RPB;
        float *h3n = hs_base + (2 * 2 + p) * H * RPB;
        const float *h3o = hs_base + (2 * 2 + q) * H * RPB;
        float *h4n = hs_base + (3 * 2 + p) * H * RPB;
        const float *h4o = hs_base + (3 * 2 + q) * H * RPB;

        if (tid < RPB) x_s[tid] = input[(b0 + tid) * T + t];
        __syncthreads();                                   // x visible; h*n(t-1) visible

        u64 acc[16];

        // ----- layer 1: x part + own part (all inputs ready at step start) -----
        acc_init(acc, bias4[0 * 80 + j]);
        {
            const ulonglong2 *xv = (const ulonglong2 *)(x_s + roff);
            fmak8(acc, w1x, xv[0], xv[1]);
        }
        gemm80p(acc, W1own, wb, h1o, j, roff);
        ldw4(wb[0], W2own, 0, j);                          // prefetch next gemm
        ldw4(wb[1], W2own, 4, j);
        cell(acc, c[0], h1n, j, roff);                     // MUFU burst covers LDGs

        // ----- layer 2: own half -> barrier -> input half -----
        acc_init(acc, bias4[1 * 80 + j]);
        gemm80p(acc, W2own, wb, h2o, j, roff);
        ldw4(wb[0], W2in, 0, j);
        ldw4(wb[1], W2in, 4, j);
        __syncthreads();                                   // h1n visible
        gemm80p(acc, W2in, wb, h1n, j, roff);
        ldw4(wb[0], W3own, 0, j);
        ldw4(wb[1], W3own, 4, j);
        cell(acc, c[1], h2n, j, roff);

        // ----- layer 3 -----
        acc_init(acc, bias4[2 * 80 + j]);
        gemm80p(acc, W3own, wb, h3o, j, roff);
        ldw4(wb[0], W3in, 0, j);
        ldw4(wb[1], W3in, 4, j);
        __syncthreads();                                   // h2n visible

        // output head: out[b, t] = w_lin . h2_new[b] + b_lin (32 threads)
        if (tid < RPB) {
            float s = blin_v;
#pragma unroll 8
            for (int jj = 0; jj < H; jj++) s = fmaf(wlin_s[jj], h2n[jj * RPB + tid], s);
            out[(b0 + tid) * T + t] = s;
        }

        gemm80p(acc, W3in, wb, h2n, j, roff);
        ldw4(wb[0], W4own, 0, j);
        ldw4(wb[1], W4own, 4, j);
        cell(acc, c[2], h3n, j, roff);

        // ----- layer 4 -----
        acc_init(acc, bias4[3 * 80 + j]);
        gemm80p(acc, W4own, wb, h4o, j, roff);
        ldw4(wb[0], W4in, 0, j);
        ldw4(wb[1], W4in, 4, j);
        __syncthreads();                                   // h3n visible
        gemm80p(acc, W4in, wb, h3n, j, roff);
        ldw4(wb[0], W1own, 0, j);                          // prefetch next step's L1
        ldw4(wb[1], W1own, 4, j);
        cell(acc, c[3], h4n, j, roff);
        // no trailing barrier: next step's top barrier orders h4n / x_s
    }
}

extern "C" void kernel_launch(void *const *d_in, const int *in_sizes, int n_in,
                              void *d_out, int out_size) {
    const float *input = (const float *)d_in[0];
    const float *wlin  = (const float *)d_in[17];
    const float *blin  = (const float *)d_in[18];

    pack_kernel<<<(WTOT + BTOT + 255) / 256, 256>>>(
        (const float *)d_in[1],  (const float *)d_in[2],  (const float *)d_in[3],  (const float *)d_in[4],
        (const float *)d_in[5],  (const float *)d_in[6],  (const float *)d_in[7],  (const float *)d_in[8],
        (const float *)d_in[9],  (const float *)d_in[10], (const float *)d_in[11], (const float *)d_in[12],
        (const float *)d_in[13], (const float *)d_in[14], (const float *)d_in[15], (const float *)d_in[16]);

    cudaFuncSetAttribute(lstm4_kernel, cudaFuncAttributeMaxDynamicSharedMemorySize, SMEM_BYTES);
    lstm4_kernel<<<NCTA, NTHR, SMEM_BYTES>>>(input, wlin, blin, (float *)d_out);
}

// round 6
// speedup vs baseline: 1.0909x; 1.0502x over previous
#include <cuda_runtime.h>

// Problem constants (fixed by setup_inputs)
#define H     80
#define B     4096
#define T     512
#define RVAL  28            // valid rows per CTA
#define SLOTS 32            // smem row-slot stride (4 rblk * 8 slots, 7 valid each)
#define NCTA  148           // one CTA per SM
#define NTHR  320           // thread = (j in [0,80), rblk in [0,4)), 7 rows each

// Packed weight layout (floats):
//   layer 1: k in [0,81)  : Wp[(k*80+j)*4 + g], k=0 -> x weight, k>=1 -> h1 weight (col k-1)
//   layer l>=2: k in [0,160): k<80 -> w_ih col k (input h_{l-1}), k>=80 -> w_hh col k-80 (own h)
#define OFF1 0
#define OFF2 25920          // 81*320
#define OFF3 77120          // OFF2 + 160*320
#define OFF4 128320
#define WTOT 179520
#define BTOT 1280           // 4 layers * 320 (bias, gate-interleaved [l][j][g])

__device__ float g_Wp[WTOT];
__device__ float g_Bp[BTOT];

typedef unsigned long long u64;

__device__ __forceinline__ u64 dup2(float w) {
    u64 r; unsigned u = __float_as_uint(w);
    asm("mov.b64 %0, {%1, %1};" : "=l"(r) : "r"(u));
    return r;
}
__device__ __forceinline__ void fma2(u64 &d, u64 a, u64 b) {
    asm("fma.rn.f32x2 %0, %1, %2, %0;" : "+l"(d) : "l"(a), "l"(b));
}
__device__ __forceinline__ float lo32(u64 v) { return __uint_as_float((unsigned)v); }
__device__ __forceinline__ float hi32(u64 v) { return __uint_as_float((unsigned)(v >> 32)); }

__device__ __forceinline__ float tanhap(float x) {
    float y; asm("tanh.approx.f32 %0, %1;" : "=f"(y) : "f"(x)); return y;
}
__device__ __forceinline__ float sigf(float x) {
    return fmaf(0.5f, tanhap(0.5f * x), 0.5f);   // sigmoid via 1 MUFU
}

// One k-slice for 7 rows: 4 gates x (3 row-pairs as f32x2 + 1 scalar row)
// a2 layout: a2[3g + p] = gate g, row pair p (rows 2p, 2p+1); a1[g] = gate g row 6
__device__ __forceinline__ void fmak7(u64 *a2, float *a1, float4 w,
                                      ulonglong2 ha, u64 hb, float hc) {
    u64 w0 = dup2(w.x), w1 = dup2(w.y), w2 = dup2(w.z), w3 = dup2(w.w);
    fma2(a2[0], w0, ha.x); fma2(a2[1],  w0, ha.y); fma2(a2[2],  w0, hb); a1[0] = fmaf(w.x, hc, a1[0]);
    fma2(a2[3], w1, ha.x); fma2(a2[4],  w1, ha.y); fma2(a2[5],  w1, hb); a1[1] = fmaf(w.y, hc, a1[1]);
    fma2(a2[6], w2, ha.x); fma2(a2[7],  w2, ha.y); fma2(a2[8],  w2, hb); a1[2] = fmaf(w.z, hc, a1[2]);
    fma2(a2[9], w3, ha.x); fma2(a2[10], w3, ha.y); fma2(a2[11], w3, hb); a1[3] = fmaf(w.w, hc, a1[3]);
}

// Load one 4-k weight chunk (4 float4) for unit j
__device__ __forceinline__ void ldw4(float4 (&wt)[4], const float4 *__restrict__ W, int k0, int j) {
#pragma unroll
    for (int q = 0; q < 4; q++) wt[q] = W[(k0 + q) * 80 + j];
}

// 80-wide gemm half with distance-2 weight prefetch (4 rotating chunk slots)
// and 1-k-ahead h prefetch. Caller must have preloaded wb[0] (k 0..3) and
// wb[1] (k 4..7) BEFORE calling.
__device__ __forceinline__ void gemm80p(u64 *a2, float *a1, const float4 *__restrict__ W,
                                        float4 (&wb)[4][4],
                                        const float *__restrict__ hsrc, int j, int roff) {
    ulonglong2 hA; u64 hB; float hC;
    {
        const float *p = hsrc + roff;
        hA = *(const ulonglong2 *)p;
        hB = *(const u64 *)(p + 4);
        hC = p[6];
    }
#pragma unroll 1
    for (int c4 = 0; c4 < 16; c4 += 4) {
#pragma unroll
        for (int u = 0; u < 4; u++) {
            const int c = c4 + u;                       // chunk index, c&3 == u
            ldw4(wb[(u + 2) & 3], W, (c + 2) * 4, j);   // prefetch chunk c+2
#pragma unroll
            for (int kq = 0; kq < 4; kq++) {
                const int k = c * 4 + kq;
                const float *p = hsrc + (k + 1) * SLOTS + roff;
                ulonglong2 nA = *(const ulonglong2 *)p;
                u64        nB = *(const u64 *)(p + 4);
                float      nC = p[6];
                fmak7(a2, a1, wb[u][kq], hA, hB, hC);
                hA = nA; hB = nB; hC = nC;
            }
        }
    }
    // epilogue: chunks 16..19 (weight prefetch only for 18,19; h stops at k=79)
#pragma unroll
    for (int u = 0; u < 4; u++) {
        const int c = 16 + u;
        if (u < 2) ldw4(wb[(u + 2) & 3], W, (c + 2) * 4, j);
#pragma unroll
        for (int kq = 0; kq < 4; kq++) {
            const int k = c * 4 + kq;
            ulonglong2 nA = hA; u64 nB = hB; float nC = hC;
            if (k < 79) {
                const float *p = hsrc + (k + 1) * SLOTS + roff;
                nA = *(const ulonglong2 *)p;
                nB = *(const u64 *)(p + 4);
                nC = p[6];
            }
            fmak7(a2, a1, wb[u][kq], hA, hB, hC);
            hA = nA; hB = nB; hC = nC;
        }
    }
}

// LSTM elementwise for 7 rows; c is 7-row cell state in registers
__device__ __forceinline__ void cell7(const u64 *a2, const float *a1,
                                      float *c, float *hdst, int j, int roff) {
    float hv[7];
#pragma unroll
    for (int qq = 0; qq < 7; qq++) {
        float iv, fv, gv, ov;
        if (qq == 6) {
            iv = a1[0]; fv = a1[1]; gv = a1[2]; ov = a1[3];
        } else {
            int pp = qq >> 1;
            if (qq & 1) {
                iv = hi32(a2[0 + pp]); fv = hi32(a2[3 + pp]);
                gv = hi32(a2[6 + pp]); ov = hi32(a2[9 + pp]);
            } else {
                iv = lo32(a2[0 + pp]); fv = lo32(a2[3 + pp]);
                gv = lo32(a2[6 + pp]); ov = lo32(a2[9 + pp]);
            }
        }
        float cc = sigf(fv) * c[qq] + sigf(iv) * tanhap(gv);
        c[qq] = cc;
        hv[qq] = sigf(ov) * tanhap(cc);
    }
    float *d = hdst + j * SLOTS + roff;
    *(float4 *)d       = make_float4(hv[0], hv[1], hv[2], hv[3]);
    *(float2 *)(d + 4) = make_float2(hv[4], hv[5]);
    d[6] = hv[6];
}

__device__ __forceinline__ void acc_init(u64 *a2, float *a1, float4 b) {
    u64 b0 = dup2(b.x), b1 = dup2(b.y), b2 = dup2(b.z), b3 = dup2(b.w);
#pragma unroll
    for (int p = 0; p < 3; p++) { a2[0 + p] = b0; a2[3 + p] = b1; a2[6 + p] = b2; a2[9 + p] = b3; }
    a1[0] = b.x; a1[1] = b.y; a1[2] = b.z; a1[3] = b.w;
}

// ---------------------------------------------------------------------------
// Weight/bias repack kernel: transpose + gate-interleave into g_Wp / g_Bp
// ---------------------------------------------------------------------------
__global__ void pack_kernel(
    const float *wih1, const float *whh1, const float *bih1, const float *bhh1,
    const float *wih2, const float *whh2, const float *bih2, const float *bhh2,
    const float *wih3, const float *whh3, const float *bih3, const float *bhh3,
    const float *wih4, const float *whh4, const float *bih4, const float *bhh4) {
    int idx = blockIdx.x * blockDim.x + threadIdx.x;
    const float *wih[4] = {wih1, wih2, wih3, wih4};
    const float *whh[4] = {whh1, whh2, whh3, whh4};
    const float *bih[4] = {bih1, bih2, bih3, bih4};
    const float *bhh[4] = {bhh1, bhh2, bhh3, bhh4};
    if (idx < WTOT) {
        int l, off;
        if (idx < OFF2)      { l = 0; off = OFF1; }
        else if (idx < OFF3) { l = 1; off = OFF2; }
        else if (idx < OFF4) { l = 2; off = OFF3; }
        else                 { l = 3; off = OFF4; }
        int e = idx - off;
        int g = e & 3;
        int j = (e >> 2) % 80;
        int k = e / 320;
        int row = g * 80 + j;
        float v;
        if (l == 0) v = (k == 0) ? wih[0][row] : whh[0][row * 80 + (k - 1)];
        else        v = (k < 80) ? wih[l][row * 80 + k] : whh[l][row * 80 + (k - 80)];
        g_Wp[idx] = v;
    } else if (idx < WTOT + BTOT) {
        int e = idx - WTOT;
        int g = e & 3;
        int j = (e >> 2) % 80;
        int l = e / 320;
        int row = g * 80 + j;
        g_Bp[e] = bih[l][row] + bhh[l][row];
    }
}

// ---------------------------------------------------------------------------
// Main persistent LSTM kernel: 148 CTAs x 28 rows (thread = unit j, 7 rows).
// Row slot s (0..31): rb = s>>3, q = s&7; valid iff q < 7; global row
// b0 + rb*7 + q. Slots 7,15,23,31 are padding for alignment.
// ---------------------------------------------------------------------------
#define SMEM_FLOATS (4 * 2 * H * SLOTS + SLOTS + H + BTOT)
#define SMEM_BYTES  (SMEM_FLOATS * 4)

__global__ void __launch_bounds__(NTHR, 1) lstm4_kernel(
    const float *__restrict__ input,  // (B, T)
    const float *__restrict__ wlin,   // (80)
    const float *__restrict__ blin,   // (1)
    float *__restrict__ out) {        // (B, T)
    extern __shared__ float sm[];
    float *hs_base = sm;                          // [4][2][80][SLOTS]
    float *x_s     = sm + 4 * 2 * H * SLOTS;      // [SLOTS]
    float *wlin_s  = x_s + SLOTS;                 // [80]
    float *bias_s  = wlin_s + H;                  // [4][80][4] gate-interleaved

    const int b0 = blockIdx.x * RVAL;
    if (b0 >= B) return;                          // fully-idle tail CTA

    const int tid  = threadIdx.x;
    const int j    = tid % 80;
    const int rblk = tid / 80;                    // 0..3
    const int roff = rblk * 8;                    // slot base (7 valid rows)

    // this thread's slot for x/out work (threads 0..31 only)
    const int srb = tid >> 3, sq = tid & 7;
    const int srow = b0 + srb * 7 + sq;           // global row for slot tid
    const bool sval = (tid < SLOTS) && (sq < 7) && (srow < B);

    for (int i = tid; i < 4 * 2 * H * SLOTS; i += NTHR) hs_base[i] = 0.0f;
    if (tid < H) wlin_s[tid] = wlin[tid];
    for (int i = tid; i < BTOT; i += NTHR) bias_s[i] = g_Bp[i];
    if (tid < SLOTS) x_s[tid] = 0.0f;
    const float blin_v = blin[0];

    float c[4][7];
#pragma unroll
    for (int l = 0; l < 4; l++)
#pragma unroll
        for (int qq = 0; qq < 7; qq++) c[l][qq] = 0.0f;

    // weight block pointers (float4[k][80], gate-interleaved)
    const float4 *W1x   = (const float4 *)(g_Wp + OFF1);           // k=0 (x slice)
    const float4 *W1own = W1x + 80;                                 // 80 k
    const float4 *W2in  = (const float4 *)(g_Wp + OFF2);            // 80 k
    const float4 *W2own = W2in + 80 * 80;
    const float4 *W3in  = (const float4 *)(g_Wp + OFF3);
    const float4 *W3own = W3in + 80 * 80;
    const float4 *W4in  = (const float4 *)(g_Wp + OFF4);
    const float4 *W4own = W4in + 80 * 80;
    const float4 *bias4 = (const float4 *)bias_s;

    float4 wb[4][4];                 // rotating weight chunk slots
    float4 w1x = W1x[j];             // x-slice weight, loop-invariant

    __syncthreads();

    // prologue prefetch for first gemm (L1 own)
    ldw4(wb[0], W1own, 0, j);
    ldw4(wb[1], W1own, 4, j);

    for (int t = 0; t < T; t++) {
        const int p = t & 1;       // write buffer this step
        const int q = p ^ 1;       // read buffer (previous step)
        float *h1n = hs_base + (0 * 2 + p) * H * SLOTS;
        const float *h1o = hs_base + (0 * 2 + q) * H * SLOTS;
        float *h2n = hs_base + (1 * 2 + p) * H * SLOTS;
        const float *h2o = hs_base + (1 * 2 + q) * H * SLOTS;
        float *h3n = hs_base + (2 * 2 + p) * H * SLOTS;
        const float *h3o = hs_base + (2 * 2 + q) * H * SLOTS;
        float *h4n = hs_base + (3 * 2 + p) * H * SLOTS;
        const float *h4o = hs_base + (3 * 2 + q) * H * SLOTS;

        if (sval) x_s[tid] = input[srow * T + t];
        __syncthreads();                                   // x visible; h*n(t-1) visible

        u64 a2[12]; float a1[4];

        // ----- layer 1: x part + own part (all inputs ready at step start) -----
        acc_init(a2, a1, bias4[0 * 80 + j]);
        {
            const float *xp = x_s + roff;
            fmak7(a2, a1, w1x, *(const ulonglong2 *)xp, *(const u64 *)(xp + 4), xp[6]);
        }
        gemm80p(a2, a1, W1own, wb, h1o, j, roff);
        ldw4(wb[0], W2own, 0, j);                          // prefetch next gemm
        ldw4(wb[1], W2own, 4, j);
        cell7(a2, a1, c[0], h1n, j, roff);                 // MUFU burst covers LDGs

        // ----- layer 2: own half -> barrier -> input half -----
        acc_init(a2, a1, bias4[1 * 80 + j]);
        gemm80p(a2, a1, W2own, wb, h2o, j, roff);
        ldw4(wb[0], W2in, 0, j);
        ldw4(wb[1], W2in, 4, j);
        __syncthreads();                                   // h1n visible
        gemm80p(a2, a1, W2in, wb, h1n, j, roff);
        ldw4(wb[0], W3own, 0, j);
        ldw4(wb[1], W3own, 4, j);
        cell7(a2, a1, c[1], h2n, j, roff);

        // ----- layer 3 -----
        acc_init(a2, a1, bias4[2 * 80 + j]);
        gemm80p(a2, a1, W3own, wb, h3o, j, roff);
        ldw4(wb[0], W3in, 0, j);
        ldw4(wb[1], W3in, 4, j);
        __syncthreads();                                   // h2n visible

        // output head: out[b, t] = w_lin . h2_new[b] + b_lin (one slot per thread)
        if (sval) {
            float s = blin_v;
#pragma unroll 8
            for (int jj = 0; jj < H; jj++) s = fmaf(wlin_s[jj], h2n[jj * SLOTS + tid], s);
            out[srow * T + t] = s;
        }

        gemm80p(a2, a1, W3in, wb, h2n, j, roff);
        ldw4(wb[0], W4own, 0, j);
        ldw4(wb[1], W4own, 4, j);
        cell7(a2, a1, c[2], h3n, j, roff);

        // ----- layer 4 -----
        acc_init(a2, a1, bias4[3 * 80 + j]);
        gemm80p(a2, a1, W4own, wb, h4o, j, roff);
        ldw4(wb[0], W4in, 0, j);
        ldw4(wb[1], W4in, 4, j);
        __syncthreads();                                   // h3n visible
        gemm80p(a2, a1, W4in, wb, h3n, j, roff);
        ldw4(wb[0], W1own, 0, j);                          // prefetch next step's L1
        ldw4(wb[1], W1own, 4, j);
        cell7(a2, a1, c[3], h4n, j, roff);
        // no trailing barrier: next step's top barrier orders h4n / x_s
    }
}

extern "C" void kernel_launch(void *const *d_in, const int *in_sizes, int n_in,
                              void *d_out, int out_size) {
    const float *input = (const float *)d_in[0];
    const float *wlin  = (const float *)d_in[17];
    const float *blin  = (const float *)d_in[18];

    pack_kernel<<<(WTOT + BTOT + 255) / 256, 256>>>(
        (const float *)d_in[1],  (const float *)d_in[2],  (const float *)d_in[3],  (const float *)d_in[4],
        (const float *)d_in[5],  (const float *)d_in[6],  (const float *)d_in[7],  (const float *)d_in[8],
        (const float *)d_in[9],  (const float *)d_in[10], (const float *)d_in[11], (const float *)d_in[12],
        (const float *)d_in[13], (const float *)d_in[14], (const float *)d_in[15], (const float *)d_in[16]);

    cudaFuncSetAttribute(lstm4_kernel, cudaFuncAttributeMaxDynamicSharedMemorySize, SMEM_BYTES);
    lstm4_kernel<<<NCTA, NTHR, SMEM_BYTES>>>(input, wlin, blin, (float *)d_out);
}

// round 7
// speedup vs baseline: 1.0911x; 1.0002x over previous
#include <cuda_runtime.h>

// Problem constants (fixed by setup_inputs)
#define H     80
#define B     4096
#define T     512
#define RVAL  28            // valid rows per CTA
#define SLOTS 32            // smem row-slot stride (4 rblk * 8 slots, 7 valid each)
#define NCTA  148           // one CTA per SM
#define NTHR  320           // thread = (j in [0,80), rblk in [0,4)), 7 rows each

// Packed weight layout (floats):
//   layer 1: k in [0,81)  : Wp[(k*80+j)*4 + g], k=0 -> x weight, k>=1 -> h1 weight (col k-1)
//   layer l>=2: k in [0,160): k<80 -> w_ih col k (input h_{l-1}), k>=80 -> w_hh col k-80 (own h)
#define OFF1 0
#define OFF2 25920          // 81*320
#define OFF3 77120          // OFF2 + 160*320
#define OFF4 128320
#define WTOT 179520
#define BTOT 1280           // 4 layers * 320 (bias, gate-interleaved [l][j][g])

__device__ float g_Wp[WTOT];
__device__ float g_Bp[BTOT];

typedef unsigned long long u64;

__device__ __forceinline__ u64 dup2(float w) {
    u64 r; unsigned u = __float_as_uint(w);
    asm("mov.b64 %0, {%1, %1};" : "=l"(r) : "r"(u));
    return r;
}
__device__ __forceinline__ void fma2(u64 &d, u64 a, u64 b) {
    asm("fma.rn.f32x2 %0, %1, %2, %0;" : "+l"(d) : "l"(a), "l"(b));
}
__device__ __forceinline__ float lo32(u64 v) { return __uint_as_float((unsigned)v); }
__device__ __forceinline__ float hi32(u64 v) { return __uint_as_float((unsigned)(v >> 32)); }

__device__ __forceinline__ float tanhap(float x) {
    float y; asm("tanh.approx.f32 %0, %1;" : "=f"(y) : "f"(x)); return y;
}
__device__ __forceinline__ float sigf(float x) {
    return fmaf(0.5f, tanhap(0.5f * x), 0.5f);   // sigmoid via 1 MUFU
}

// One k-slice for 7 rows: 4 gates x (3 row-pairs as f32x2 + 1 scalar row)
// a2 layout: a2[3g + p] = gate g, row pair p (rows 2p, 2p+1); a1[g] = gate g row 6
__device__ __forceinline__ void fmak7(u64 *a2, float *a1, float4 w,
                                      ulonglong2 ha, u64 hb, float hc) {
    u64 w0 = dup2(w.x), w1 = dup2(w.y), w2 = dup2(w.z), w3 = dup2(w.w);
    fma2(a2[0], w0, ha.x); fma2(a2[1],  w0, ha.y); fma2(a2[2],  w0, hb); a1[0] = fmaf(w.x, hc, a1[0]);
    fma2(a2[3], w1, ha.x); fma2(a2[4],  w1, ha.y); fma2(a2[5],  w1, hb); a1[1] = fmaf(w.y, hc, a1[1]);
    fma2(a2[6], w2, ha.x); fma2(a2[7],  w2, ha.y); fma2(a2[8],  w2, hb); a1[2] = fmaf(w.z, hc, a1[2]);
    fma2(a2[9], w3, ha.x); fma2(a2[10], w3, ha.y); fma2(a2[11], w3, hb); a1[3] = fmaf(w.w, hc, a1[3]);
}

// Load one 4-k weight chunk (4 float4) for unit j
__device__ __forceinline__ void ldw4(float4 (&wt)[4], const float4 *__restrict__ W, int k0, int j) {
#pragma unroll
    for (int q = 0; q < 4; q++) wt[q] = W[(k0 + q) * 80 + j];
}

// 80-wide gemm half with distance-2 weight prefetch (4 rotating chunk slots)
// and 1-k-ahead h prefetch. Caller must have preloaded wb[0] (k 0..3) and
// wb[1] (k 4..7) BEFORE calling.
__device__ __forceinline__ void gemm80p(u64 *a2, float *a1, const float4 *__restrict__ W,
                                        float4 (&wb)[4][4],
                                        const float *__restrict__ hsrc, int j, int roff) {
    ulonglong2 hA; u64 hB; float hC;
    {
        const float *p = hsrc + roff;
        hA = *(const ulonglong2 *)p;
        hB = *(const u64 *)(p + 4);
        hC = p[6];
    }
#pragma unroll 1
    for (int c4 = 0; c4 < 16; c4 += 4) {
#pragma unroll
        for (int u = 0; u < 4; u++) {
            const int c = c4 + u;                       // chunk index, c&3 == u
            ldw4(wb[(u + 2) & 3], W, (c + 2) * 4, j);   // prefetch chunk c+2
#pragma unroll
            for (int kq = 0; kq < 4; kq++) {
                const int k = c * 4 + kq;
                const float *p = hsrc + (k + 1) * SLOTS + roff;
                ulonglong2 nA = *(const ulonglong2 *)p;
                u64        nB = *(const u64 *)(p + 4);
                float      nC = p[6];
                fmak7(a2, a1, wb[u][kq], hA, hB, hC);
                hA = nA; hB = nB; hC = nC;
            }
        }
    }
    // epilogue: chunks 16..19 (weight prefetch only for 18,19; h stops at k=79)
#pragma unroll
    for (int u = 0; u < 4; u++) {
        const int c = 16 + u;
        if (u < 2) ldw4(wb[(u + 2) & 3], W, (c + 2) * 4, j);
#pragma unroll
        for (int kq = 0; kq < 4; kq++) {
            const int k = c * 4 + kq;
            ulonglong2 nA = hA; u64 nB = hB; float nC = hC;
            if (k < 79) {
                const float *p = hsrc + (k + 1) * SLOTS + roff;
                nA = *(const ulonglong2 *)p;
                nB = *(const u64 *)(p + 4);
                nC = p[6];
            }
            fmak7(a2, a1, wb[u][kq], hA, hB, hC);
            hA = nA; hB = nB; hC = nC;
        }
    }
}

// LSTM elementwise for 7 rows; c is 7-row cell state in registers
__device__ __forceinline__ void cell7(const u64 *a2, const float *a1,
                                      float *c, float *hdst, int j, int roff) {
    float hv[7];
#pragma unroll
    for (int qq = 0; qq < 7; qq++) {
        float iv, fv, gv, ov;
        if (qq == 6) {
            iv = a1[0]; fv = a1[1]; gv = a1[2]; ov = a1[3];
        } else {
            int pp = qq >> 1;
            if (qq & 1) {
                iv = hi32(a2[0 + pp]); fv = hi32(a2[3 + pp]);
                gv = hi32(a2[6 + pp]); ov = hi32(a2[9 + pp]);
            } else {
                iv = lo32(a2[0 + pp]); fv = lo32(a2[3 + pp]);
                gv = lo32(a2[6 + pp]); ov = lo32(a2[9 + pp]);
            }
        }
        float cc = sigf(fv) * c[qq] + sigf(iv) * tanhap(gv);
        c[qq] = cc;
        hv[qq] = sigf(ov) * tanhap(cc);
    }
    float *d = hdst + j * SLOTS + roff;
    *(float4 *)d       = make_float4(hv[0], hv[1], hv[2], hv[3]);
    *(float2 *)(d + 4) = make_float2(hv[4], hv[5]);
    d[6] = hv[6];
}

__device__ __forceinline__ void acc_init(u64 *a2, float *a1, float4 b) {
    u64 b0 = dup2(b.x), b1 = dup2(b.y), b2 = dup2(b.z), b3 = dup2(b.w);
#pragma unroll
    for (int p = 0; p < 3; p++) { a2[0 + p] = b0; a2[3 + p] = b1; a2[6 + p] = b2; a2[9 + p] = b3; }
    a1[0] = b.x; a1[1] = b.y; a1[2] = b.z; a1[3] = b.w;
}

// ---------------------------------------------------------------------------
// Weight/bias repack kernel: transpose + gate-interleave into g_Wp / g_Bp
// ---------------------------------------------------------------------------
__global__ void pack_kernel(
    const float *wih1, const float *whh1, const float *bih1, const float *bhh1,
    const float *wih2, const float *whh2, const float *bih2, const float *bhh2,
    const float *wih3, const float *whh3, const float *bih3, const float *bhh3,
    const float *wih4, const float *whh4, const float *bih4, const float *bhh4) {
    int idx = blockIdx.x * blockDim.x + threadIdx.x;
    const float *wih[4] = {wih1, wih2, wih3, wih4};
    const float *whh[4] = {whh1, whh2, whh3, whh4};
    const float *bih[4] = {bih1, bih2, bih3, bih4};
    const float *bhh[4] = {bhh1, bhh2, bhh3, bhh4};
    if (idx < WTOT) {
        int l, off;
        if (idx < OFF2)      { l = 0; off = OFF1; }
        else if (idx < OFF3) { l = 1; off = OFF2; }
        else if (idx < OFF4) { l = 2; off = OFF3; }
        else                 { l = 3; off = OFF4; }
        int e = idx - off;
        int g = e & 3;
        int j = (e >> 2) % 80;
        int k = e / 320;
        int row = g * 80 + j;
        float v;
        if (l == 0) v = (k == 0) ? wih[0][row] : whh[0][row * 80 + (k - 1)];
        else        v = (k < 80) ? wih[l][row * 80 + k] : whh[l][row * 80 + (k - 80)];
        g_Wp[idx] = v;
    } else if (idx < WTOT + BTOT) {
        int e = idx - WTOT;
        int g = e & 3;
        int j = (e >> 2) % 80;
        int l = e / 320;
        int row = g * 80 + j;
        g_Bp[e] = bih[l][row] + bhh[l][row];
    }
}

// ---------------------------------------------------------------------------
// Main persistent LSTM kernel: 148 CTAs x 28 rows (thread = unit j, 7 rows).
// Row slot s (0..31): rb = s>>3, q = s&7; valid iff q < 7; global row
// b0 + rb*7 + q. Slots 7,15,23,31 are padding for alignment.
// ---------------------------------------------------------------------------
#define SMEM_FLOATS (4 * 2 * H * SLOTS + SLOTS + H + BTOT)
#define SMEM_BYTES  (SMEM_FLOATS * 4)

__global__ void __launch_bounds__(NTHR, 1) lstm4_kernel(
    const float *__restrict__ input,  // (B, T)
    const float *__restrict__ wlin,   // (80)
    const float *__restrict__ blin,   // (1)
    float *__restrict__ out) {        // (B, T)
    extern __shared__ float sm[];
    float *hs_base = sm;                          // [4][2][80][SLOTS]
    float *x_s     = sm + 4 * 2 * H * SLOTS;      // [SLOTS]
    float *wlin_s  = x_s + SLOTS;                 // [80]
    float *bias_s  = wlin_s + H;                  // [4][80][4] gate-interleaved

    const int b0 = blockIdx.x * RVAL;
    if (b0 >= B) return;                          // fully-idle tail CTA

    const int tid  = threadIdx.x;
    const int j    = tid % 80;
    const int rblk = tid / 80;                    // 0..3
    const int roff = rblk * 8;                    // slot base (7 valid rows)

    // this thread's slot for x/out work (threads 0..31 only)
    const int srb = tid >> 3, sq = tid & 7;
    const int srow = b0 + srb * 7 + sq;           // global row for slot tid
    const bool sval = (tid < SLOTS) && (sq < 7) && (srow < B);

    for (int i = tid; i < 4 * 2 * H * SLOTS; i += NTHR) hs_base[i] = 0.0f;
    if (tid < H) wlin_s[tid] = wlin[tid];
    for (int i = tid; i < BTOT; i += NTHR) bias_s[i] = g_Bp[i];
    if (tid < SLOTS) x_s[tid] = 0.0f;
    const float blin_v = blin[0];

    float c[4][7];
#pragma unroll
    for (int l = 0; l < 4; l++)
#pragma unroll
        for (int qq = 0; qq < 7; qq++) c[l][qq] = 0.0f;

    // weight block pointers (float4[k][80], gate-interleaved)
    const float4 *W1x   = (const float4 *)(g_Wp + OFF1);           // k=0 (x slice)
    const float4 *W1own = W1x + 80;                                 // 80 k
    const float4 *W2in  = (const float4 *)(g_Wp + OFF2);            // 80 k
    const float4 *W2own = W2in + 80 * 80;
    const float4 *W3in  = (const float4 *)(g_Wp + OFF3);
    const float4 *W3own = W3in + 80 * 80;
    const float4 *W4in  = (const float4 *)(g_Wp + OFF4);
    const float4 *W4own = W4in + 80 * 80;
    const float4 *bias4 = (const float4 *)bias_s;

    float4 wb[4][4];                 // rotating weight chunk slots
    float4 w1x = W1x[j];             // x-slice weight, loop-invariant

    __syncthreads();

    // prologue prefetch for first gemm (L1 own)
    ldw4(wb[0], W1own, 0, j);
    ldw4(wb[1], W1own, 4, j);

    for (int t = 0; t < T; t++) {
        const int p = t & 1;       // write buffer this step
        const int q = p ^ 1;       // read buffer (previous step)
        float *h1n = hs_base + (0 * 2 + p) * H * SLOTS;
        const float *h1o = hs_base + (0 * 2 + q) * H * SLOTS;
        float *h2n = hs_base + (1 * 2 + p) * H * SLOTS;
        const float *h2o = hs_base + (1 * 2 + q) * H * SLOTS;
        float *h3n = hs_base + (2 * 2 + p) * H * SLOTS;
        const float *h3o = hs_base + (2 * 2 + q) * H * SLOTS;
        float *h4n = hs_base + (3 * 2 + p) * H * SLOTS;
        const float *h4o = hs_base + (3 * 2 + q) * H * SLOTS;

        if (sval) x_s[tid] = input[srow * T + t];
        __syncthreads();                                   // x visible; h*n(t-1) visible

        u64 a2[12]; float a1[4];

        // ----- layer 1: x part + own part (all inputs ready at step start) -----
        acc_init(a2, a1, bias4[0 * 80 + j]);
        {
            const float *xp = x_s + roff;
            fmak7(a2, a1, w1x, *(const ulonglong2 *)xp, *(const u64 *)(xp + 4), xp[6]);
        }
        gemm80p(a2, a1, W1own, wb, h1o, j, roff);
        ldw4(wb[0], W2own, 0, j);                          // prefetch next gemm
        ldw4(wb[1], W2own, 4, j);
        cell7(a2, a1, c[0], h1n, j, roff);                 // MUFU burst covers LDGs

        // ----- layer 2: own half -> barrier -> input half -----
        acc_init(a2, a1, bias4[1 * 80 + j]);
        gemm80p(a2, a1, W2own, wb, h2o, j, roff);
        ldw4(wb[0], W2in, 0, j);
        ldw4(wb[1], W2in, 4, j);
        __syncthreads();                                   // h1n visible
        gemm80p(a2, a1, W2in, wb, h1n, j, roff);
        ldw4(wb[0], W3own, 0, j);
        ldw4(wb[1], W3own, 4, j);
        cell7(a2, a1, c[1], h2n, j, roff);

        // ----- layer 3 -----
        acc_init(a2, a1, bias4[2 * 80 + j]);
        gemm80p(a2, a1, W3own, wb, h3o, j, roff);
        ldw4(wb[0], W3in, 0, j);
        ldw4(wb[1], W3in, 4, j);
        __syncthreads();                                   // h2n visible

        // output head: out[b, t] = w_lin . h2_new[b] + b_lin (one slot per thread)
        if (sval) {
            float s = blin_v;
#pragma unroll 8
            for (int jj = 0; jj < H; jj++) s = fmaf(wlin_s[jj], h2n[jj * SLOTS + tid], s);
            out[srow * T + t] = s;
        }

        gemm80p(a2, a1, W3in, wb, h2n, j, roff);
        ldw4(wb[0], W4own, 0, j);
        ldw4(wb[1], W4own, 4, j);
        cell7(a2, a1, c[2], h3n, j, roff);

        // ----- layer 4 -----
        acc_init(a2, a1, bias4[3 * 80 + j]);
        gemm80p(a2, a1, W4own, wb, h4o, j, roff);
        ldw4(wb[0], W4in, 0, j);
        ldw4(wb[1], W4in, 4, j);
        __syncthreads();                                   // h3n visible
        gemm80p(a2, a1, W4in, wb, h3n, j, roff);
        ldw4(wb[0], W1own, 0, j);                          // prefetch next step's L1
        ldw4(wb[1], W1own, 4, j);
        cell7(a2, a1, c[3], h4n, j, roff);
        // no trailing barrier: next step's top barrier orders h4n / x_s
    }
}

extern "C" void kernel_launch(void *const *d_in, const int *in_sizes, int n_in,
                              void *d_out, int out_size) {
    const float *input = (const float *)d_in[0];
    const float *wlin  = (const float *)d_in[17];
    const float *blin  = (const float *)d_in[18];

    pack_kernel<<<(WTOT + BTOT + 255) / 256, 256>>>(
        (const float *)d_in[1],  (const float *)d_in[2],  (const float *)d_in[3],  (const float *)d_in[4],
        (const float *)d_in[5],  (const float *)d_in[6],  (const float *)d_in[7],  (const float *)d_in[8],
        (const float *)d_in[9],  (const float *)d_in[10], (const float *)d_in[11], (const float *)d_in[12],
        (const float *)d_in[13], (const float *)d_in[14], (const float *)d_in[15], (const float *)d_in[16]);

    cudaFuncSetAttribute(lstm4_kernel, cudaFuncAttributeMaxDynamicSharedMemorySize, SMEM_BYTES);
    lstm4_kernel<<<NCTA, NTHR, SMEM_BYTES>>>(input, wlin, blin, (float *)d_out);
}